// round 11
// baseline (speedup 1.0000x reference)
#include <cuda_runtime.h>
#include <cuda_bf16.h>

#define HIMG 240
#define WIMG 135
#define HW   (HIMG * WIMG)
#define NF   1000
#define NV   600
#define INV_SIGMA 1.0e4f
#define BLURF 9.210240366975849e-4f
#define BAND  0.05f

#define TS     16                    // tile size in pixels
#define NTX    9                     // ceil(135/16)
#define NTY    15                    // 240/16
#define NTILES (NTX * NTY)           // 135
#define CAP    1024                  // max faces per tile list
#define CHUNK  384                   // faces staged in smem per pass

// FD packed as 5 float4:
// [0] ax ay bx by   [1] cx cy e0x e0y   [2] e1x e1y e2x e2y
// [3] rl0 rl1 rl2 rd0   [4] rd1 rd2 pad pad
struct __align__(16) FD20 { float4 q[5]; };

__device__ FD20 g_face[NF];
__device__ int  g_cnt[NTILES];           // zero at load; shade self-cleans
__device__ int  g_list[NTILES * CAP];

// ---------------------------------------------------------------------------
// Kernel A: per-face setup + tile binning
// ---------------------------------------------------------------------------
__global__ void __launch_bounds__(32)
prep_bin_kernel(const float* __restrict__ verts,
                const int*   __restrict__ faces,
                float* __restrict__ out) {
    int f = blockIdx.x * 32 + threadIdx.x;
    if (f == 0) out[0] = 0.0f;
    if (f >= NF) return;

    int idx[3];
    idx[0] = faces[3 * f + 0];
    idx[1] = faces[3 * f + 1];
    idx[2] = faces[3 * f + 2];

    float Px[3], Py[3], zs[3];
#pragma unroll
    for (int k = 0; k < 3; k++) {
        float x = verts[3 * idx[k] + 0];
        float y = verts[3 * idx[k] + 1];
        float z = verts[3 * idx[k] + 2];
        float vx = -x, vy = -y, vz = z;          // R = diag(-1,-1,1)
        zs[k] = vz;
        float zz = fmaxf(vz, 1e-6f);
        Px[k] = (__fdividef(1000.0f * vx, zz) + 512.0f) * ((float)WIMG / 1024.0f);
        Py[k] = (__fdividef(1000.0f * vy, zz) + 512.0f) * ((float)HIMG / 1024.0f);
    }
    float tz = (zs[0] + zs[1] + zs[2]) * (1.0f / 3.0f);
    if (!(tz > 1e-6f)) return;                    // culled: not binned

    float ax = Px[0], ay = Py[0];
    float bx = Px[1], by = Py[1];
    float cx = Px[2], cy = Py[2];
    float e0x = bx - ax, e0y = by - ay;
    float e1x = cx - bx, e1y = cy - by;
    float e2x = ax - cx, e2y = ay - cy;
    float l0 = e0x * e0x + e0y * e0y + 1e-12f;
    float l1 = e1x * e1x + e1y * e1y + 1e-12f;
    float l2 = e2x * e2x + e2y * e2y + 1e-12f;
    float rl0 = rsqrtf(l0), rl1 = rsqrtf(l1), rl2 = rsqrtf(l2);

    FD20 fd;
    fd.q[0] = make_float4(ax, ay, bx, by);
    fd.q[1] = make_float4(cx, cy, e0x, e0y);
    fd.q[2] = make_float4(e1x, e1y, e2x, e2y);
    fd.q[3] = make_float4(rl0, rl1, rl2, rl0 * rl0);
    fd.q[4] = make_float4(rl1 * rl1, rl2 * rl2, 0.0f, 0.0f);
    g_face[f] = fd;

    float minx = fminf(ax, fminf(bx, cx));
    float maxx = fmaxf(ax, fmaxf(bx, cx));
    float miny = fminf(ay, fminf(by, cy));
    float maxy = fmaxf(ay, fmaxf(by, cy));
    int x0 = max(0, (int)floorf(minx) - 1);
    int x1 = min(WIMG - 1, (int)ceilf(maxx));
    int y0 = max(0, (int)floorf(miny) - 1);
    int y1 = min(HIMG - 1, (int)ceilf(maxy));
    if (x1 < x0 || y1 < y0) return;
    // point-degenerate face: reference marks every pixel inside
    if (e0x == 0.0f && e0y == 0.0f && e1x == 0.0f && e1y == 0.0f) {
        x0 = 0; x1 = WIMG - 1; y0 = 0; y1 = HIMG - 1;
    }

    int tx0 = x0 >> 4, tx1 = x1 >> 4;
    int ty0 = y0 >> 4, ty1 = y1 >> 4;
    for (int ty = ty0; ty <= ty1; ty++)
        for (int tx = tx0; tx <= tx1; tx++) {
            int t = ty * NTX + tx;
            int slot = atomicAdd(&g_cnt[t], 1);
            if (slot < CAP) g_list[t * CAP + slot] = f;
        }
}

// ---------------------------------------------------------------------------
// Kernel B: one block per 16x16 tile; scan tile's face list with early exit.
// ---------------------------------------------------------------------------
__global__ void __launch_bounds__(256)
shade_kernel(const float* __restrict__ gt,
             float* __restrict__ out /* [0]=loss, [1..]=sil */) {
    __shared__ float4 sf[CHUNK * 5];
    __shared__ float  ws[8];

    const int tile = blockIdx.x;
    const int tx   = tile % NTX;
    const int ty   = tile / NTX;
    const int tid  = threadIdx.x;
    const int lane = tid & 31;
    const int warp = tid >> 5;

    const int ix = tx * TS + (tid & 15);
    const int iy = ty * TS + (tid >> 4);
    const bool valid = (ix < WIMG);               // iy always < HIMG
    const float px = (float)ix + 0.5f;
    const float py = (float)iy + 0.5f;

    int cnt = min(g_cnt[tile], CAP);

    float sum = 0.0f;
    bool covered = false;

    for (int base = 0; base < cnt; base += CHUNK) {
        int m = min(CHUNK, cnt - base);

        // stage m FDs into smem (5 float4 each)
        for (int s = tid; s < m; s += 256) {
            int f = g_list[tile * CAP + base + s];
            const float4* src = g_face[f].q;
            sf[s * 5 + 0] = src[0];
            sf[s * 5 + 1] = src[1];
            sf[s * 5 + 2] = src[2];
            sf[s * 5 + 3] = src[3];
            sf[s * 5 + 4] = src[4];
        }
        __syncthreads();

        for (int j = 0; j < m; j++) {
            if (__all_sync(0xffffffffu, covered || !valid)) break;
            if (valid && !covered) {
                float4 A0 = sf[j * 5 + 0];
                float4 A1 = sf[j * 5 + 1];
                float4 A2 = sf[j * 5 + 2];
                float4 A3 = sf[j * 5 + 3];
                float4 A4 = sf[j * 5 + 4];
                float ax = A0.x, ay = A0.y, bx = A0.z, by = A0.w;
                float cx = A1.x, cy = A1.y, e0x = A1.z, e0y = A1.w;
                float e1x = A2.x, e1y = A2.y, e2x = A2.z, e2y = A2.w;
                float rl0 = A3.x, rl1 = A3.y, rl2 = A3.z, rd0 = A3.w;
                float rd1 = A4.x, rd2 = A4.y;

                float apx0 = px - ax, apy0 = py - ay;
                float apx1 = px - bx, apy1 = py - by;
                float apx2 = px - cx, apy2 = py - cy;

                float c0 = e0x * apy0 - e0y * apx0;
                float c1 = e1x * apy1 - e1y * apx1;
                float c2 = e2x * apy2 - e2y * apx2;
                bool inside = (c0 >= 0.0f && c1 >= 0.0f && c2 >= 0.0f) ||
                              (c0 <= 0.0f && c1 <= 0.0f && c2 <= 0.0f);

                float dl = fminf(fabsf(c0) * rl0,
                           fminf(fabsf(c1) * rl1, fabsf(c2) * rl2));

                if (inside && dl > BAND) {
                    covered = true;               // alpha saturates to 1
                } else if (inside || dl <= BAND) {
                    float t0 = fminf(fmaxf((apx0 * e0x + apy0 * e0y) * rd0, 0.0f), 1.0f);
                    float rx = apx0 - t0 * e0x;
                    float ry = apy0 - t0 * e0y;
                    float d2min = rx * rx + ry * ry;

                    float t1 = fminf(fmaxf((apx1 * e1x + apy1 * e1y) * rd1, 0.0f), 1.0f);
                    rx = apx1 - t1 * e1x;
                    ry = apy1 - t1 * e1y;
                    d2min = fminf(d2min, rx * rx + ry * ry);

                    float t2 = fminf(fmaxf((apx2 * e2x + apy2 * e2y) * rd2, 0.0f), 1.0f);
                    rx = apx2 - t2 * e2x;
                    ry = apy2 - t2 * e2y;
                    d2min = fminf(d2min, rx * rx + ry * ry);

                    if (inside || d2min <= BLURF) {
                        float u = (inside ? d2min : -d2min) * INV_SIGMA;
                        // log1p(-sigmoid(u)) == -softplus(u)
                        float sp = (u > 15.0f) ? u : log1pf(__expf(u));
                        sum -= sp;
                    }
                }
                // outside & dl > BAND: d2 > BLURF -> reference-invalid
            }
        }

        // block-uniform: stop loading chunks if every pixel is covered
        if (__syncthreads_and((int)(covered || !valid))) break;
    }

    float local = 0.0f;
    if (valid) {
        float alpha = covered ? 1.0f : (1.0f - expf(sum));
        out[1 + iy * WIMG + ix] = alpha;
        local = fabsf(alpha - gt[iy * WIMG + ix]);
    }
#pragma unroll
    for (int o = 16; o > 0; o >>= 1)
        local += __shfl_down_sync(0xffffffffu, local, o);
    if (lane == 0) ws[warp] = local;
    __syncthreads();
    if (warp == 0) {
        float v = (lane < 8) ? ws[lane] : 0.0f;
#pragma unroll
        for (int o = 4; o > 0; o >>= 1)
            v += __shfl_down_sync(0xffu, v, o);
        if (lane == 0)
            atomicAdd(out, v * (1.0f / (float)HW));
    }

    if (tid == 0) g_cnt[tile] = 0;    // self-clean for next graph replay
}

// ---------------------------------------------------------------------------
extern "C" void kernel_launch(void* const* d_in, const int* in_sizes, int n_in,
                              void* d_out, int out_size) {
    const float* verts = nullptr;
    const float* gt    = nullptr;
    const int*   faces = nullptr;
    for (int i = 0; i < n_in; i++) {
        if (in_sizes[i] == NV * 3)      verts = (const float*)d_in[i];
        else if (in_sizes[i] == HW)     gt    = (const float*)d_in[i];
        else if (in_sizes[i] == NF * 3) faces = (const int*)d_in[i];
    }
    float* out = (float*)d_out;
    (void)out_size;
    prep_bin_kernel<<<(NF + 31) / 32, 32>>>(verts, faces, out);
    shade_kernel<<<NTILES, 256>>>(gt, out);
}

// round 12
// speedup vs baseline: 5.4978x; 5.4978x over previous
#include <cuda_runtime.h>
#include <cuda_bf16.h>

#define HIMG 240
#define WIMG 135
#define HW   (HIMG * WIMG)
#define NF   1000
#define NV   600
#define INV_SIGMA 1.0e4f
#define BLURF 9.210240366975849e-4f
#define BAND  0.05f

#define NT     128                 // 4 warps
#define SPLIT  8                   // row-slices per face
#define NRAST  (NF * SPLIT)        // 8000 raster blocks

struct __align__(16) FD {
    float ax, ay, bx, by, cx, cy;
    float e0x, e0y, e1x, e1y, e2x, e2y;
    float rl0, rl1, rl2, rd0, rd1, rd2;
    int x0, x1, y0, y1;
    int skip;
};

__device__ float g_sum[HW];   // zero at module load; finalize self-cleans
__device__ float g_flag[HW];  // zero at module load; finalize self-cleans

// ---------------------------------------------------------------------------
// Raster: grid NF*SPLIT. Block handles rows of its face whose bbox-relative
// index === slice (mod SPLIT). Setup once per block (warp 0 -> smem).
// ---------------------------------------------------------------------------
__global__ void __launch_bounds__(NT)
raster_kernel(const float* __restrict__ verts,
              const int*   __restrict__ faces,
              float* __restrict__ out) {
    __shared__ FD sfd;

    const int tid  = threadIdx.x;
    const int lane = tid & 31;
    const int warp = tid >> 5;                  // 0..3
    const int bid  = blockIdx.x;
    const int f    = bid >> 3;                  // SPLIT == 8
    const int sl   = bid & 7;

    if (bid == 0 && tid == 0) out[0] = 0.0f;    // loss accumulator

    // ---- setup: warp 0 only (broadcast loads), smem publish ----
    if (warp == 0) {
        int idx[3];
        idx[0] = faces[3 * f + 0];
        idx[1] = faces[3 * f + 1];
        idx[2] = faces[3 * f + 2];

        float Px[3], Py[3], zs[3];
#pragma unroll
        for (int k = 0; k < 3; k++) {
            float x = verts[3 * idx[k] + 0];
            float y = verts[3 * idx[k] + 1];
            float z = verts[3 * idx[k] + 2];
            float vx = -x, vy = -y, vz = z;     // R = diag(-1,-1,1)
            zs[k] = vz;
            float zz = fmaxf(vz, 1e-6f);
            Px[k] = (__fdividef(1000.0f * vx, zz) + 512.0f) * ((float)WIMG / 1024.0f);
            Py[k] = (__fdividef(1000.0f * vy, zz) + 512.0f) * ((float)HIMG / 1024.0f);
        }
        float tz = (zs[0] + zs[1] + zs[2]) * (1.0f / 3.0f);

        FD fd;
        fd.ax = Px[0]; fd.ay = Py[0];
        fd.bx = Px[1]; fd.by = Py[1];
        fd.cx = Px[2]; fd.cy = Py[2];
        fd.e0x = fd.bx - fd.ax; fd.e0y = fd.by - fd.ay;
        fd.e1x = fd.cx - fd.bx; fd.e1y = fd.cy - fd.by;
        fd.e2x = fd.ax - fd.cx; fd.e2y = fd.ay - fd.cy;
        float l0 = fd.e0x * fd.e0x + fd.e0y * fd.e0y + 1e-12f;
        float l1 = fd.e1x * fd.e1x + fd.e1y * fd.e1y + 1e-12f;
        float l2 = fd.e2x * fd.e2x + fd.e2y * fd.e2y + 1e-12f;
        fd.rl0 = rsqrtf(l0); fd.rl1 = rsqrtf(l1); fd.rl2 = rsqrtf(l2);
        fd.rd0 = fd.rl0 * fd.rl0;
        fd.rd1 = fd.rl1 * fd.rl1;
        fd.rd2 = fd.rl2 * fd.rl2;

        fd.skip = !(tz > 1e-6f);
        if (!fd.skip) {
            float minx = fminf(fd.ax, fminf(fd.bx, fd.cx));
            float maxx = fmaxf(fd.ax, fmaxf(fd.bx, fd.cx));
            float miny = fminf(fd.ay, fminf(fd.by, fd.cy));
            float maxy = fmaxf(fd.ay, fmaxf(fd.by, fd.cy));
            fd.x0 = max(0, (int)floorf(minx) - 1);
            fd.x1 = min(WIMG - 1, (int)ceilf(maxx));
            fd.y0 = max(0, (int)floorf(miny) - 1);
            fd.y1 = min(HIMG - 1, (int)ceilf(maxy));
            // point-degenerate face: reference marks every pixel inside
            if (fd.e0x == 0.0f && fd.e0y == 0.0f &&
                fd.e1x == 0.0f && fd.e1y == 0.0f) {
                fd.x0 = 0; fd.x1 = WIMG - 1; fd.y0 = 0; fd.y1 = HIMG - 1;
            }
        } else {
            fd.x0 = 1; fd.x1 = 0; fd.y0 = 1; fd.y1 = 0;
        }
        if (lane == 0) sfd = fd;
    }
    __syncthreads();
    const FD fd = sfd;
    if (fd.skip) return;

    // ---- sweep rows with (row - y0) % SPLIT == sl; 4 warps stride --------
    const int nrows = fd.y1 - fd.y0 + 1;
    for (int r = sl + warp * SPLIT; r < nrows; r += 4 * SPLIT) {
        int   iy  = fd.y0 + r;
        float py  = (float)iy + 0.5f;
        int   row = iy * WIMG;
        for (int ix = fd.x0 + lane; ix <= fd.x1; ix += 32) {
            float px = (float)ix + 0.5f;

            float apx0 = px - fd.ax, apy0 = py - fd.ay;
            float apx1 = px - fd.bx, apy1 = py - fd.by;
            float apx2 = px - fd.cx, apy2 = py - fd.cy;

            float c0 = fd.e0x * apy0 - fd.e0y * apx0;
            float c1 = fd.e1x * apy1 - fd.e1y * apx1;
            float c2 = fd.e2x * apy2 - fd.e2y * apx2;
            bool inside = (c0 >= 0.0f && c1 >= 0.0f && c2 >= 0.0f) ||
                          (c0 <= 0.0f && c1 <= 0.0f && c2 <= 0.0f);

            // conservative perpendicular line distance (<= segment distance)
            float dl = fminf(fabsf(c0) * fd.rl0,
                       fminf(fabsf(c1) * fd.rl1, fabsf(c2) * fd.rl2));

            if (inside && dl > BAND) {
                // log contribution <= -25: alpha saturates -> idempotent flag
                g_flag[row + ix] = 1.0f;
            } else if (inside || dl <= BAND) {
                // exact reference math (segment distances)
                float t0 = fminf(fmaxf((apx0 * fd.e0x + apy0 * fd.e0y) * fd.rd0, 0.0f), 1.0f);
                float rx = apx0 - t0 * fd.e0x;
                float ry = apy0 - t0 * fd.e0y;
                float d2min = rx * rx + ry * ry;

                float t1 = fminf(fmaxf((apx1 * fd.e1x + apy1 * fd.e1y) * fd.rd1, 0.0f), 1.0f);
                rx = apx1 - t1 * fd.e1x;
                ry = apy1 - t1 * fd.e1y;
                d2min = fminf(d2min, rx * rx + ry * ry);

                float t2 = fminf(fmaxf((apx2 * fd.e2x + apy2 * fd.e2y) * fd.rd2, 0.0f), 1.0f);
                rx = apx2 - t2 * fd.e2x;
                ry = apy2 - t2 * fd.e2y;
                d2min = fminf(d2min, rx * rx + ry * ry);

                if (inside || d2min <= BLURF) {
                    float u = (inside ? d2min : -d2min) * INV_SIGMA;
                    // log1p(-sigmoid(u)) == -softplus(u)
                    float sp = (u > 15.0f) ? u : log1pf(__expf(u));
                    if (sp != 0.0f) atomicAdd(&g_sum[row + ix], -sp);
                }
            }
            // outside & dl > BAND: d2min >= dl^2 > BLURF -> reference-invalid
        }
    }
}

// ---------------------------------------------------------------------------
// Finalize (PDL secondary): waits on the raster grid, then computes alpha,
// sil, loss; self-cleans accumulators for the next graph replay.
// ---------------------------------------------------------------------------
__global__ void __launch_bounds__(256)
finalize_kernel(const float* __restrict__ gt,
                float* __restrict__ out) {
    // Block until the primary (raster) grid has fully completed; guarantees
    // visibility of all its memory writes.
    cudaGridDependencySynchronize();

    int i = blockIdx.x * blockDim.x + threadIdx.x;
    float local = 0.0f;
    if (i < HW) {
        float s  = g_sum[i];
        float fl = g_flag[i];
        g_sum[i]  = 0.0f;
        g_flag[i] = 0.0f;
        float alpha = (fl != 0.0f) ? 1.0f : (1.0f - expf(s));
        out[1 + i] = alpha;
        local = fabsf(alpha - gt[i]);
    }
#pragma unroll
    for (int o = 16; o > 0; o >>= 1)
        local += __shfl_down_sync(0xffffffffu, local, o);

    __shared__ float ws[8];
    int lane = threadIdx.x & 31;
    int wid  = threadIdx.x >> 5;
    if (lane == 0) ws[wid] = local;
    __syncthreads();
    if (wid == 0) {
        local = (lane < 8) ? ws[lane] : 0.0f;
#pragma unroll
        for (int o = 4; o > 0; o >>= 1)
            local += __shfl_down_sync(0xffu, local, o);
        if (lane == 0)
            atomicAdd(out, local * (1.0f / (float)HW));
    }
}

// ---------------------------------------------------------------------------
extern "C" void kernel_launch(void* const* d_in, const int* in_sizes, int n_in,
                              void* d_out, int out_size) {
    const float* verts = nullptr;
    const float* gt    = nullptr;
    const int*   faces = nullptr;
    for (int i = 0; i < n_in; i++) {
        if (in_sizes[i] == NV * 3)      verts = (const float*)d_in[i];
        else if (in_sizes[i] == HW)     gt    = (const float*)d_in[i];
        else if (in_sizes[i] == NF * 3) faces = (const int*)d_in[i];
    }
    float* out = (float*)d_out;
    (void)out_size;

    raster_kernel<<<NRAST, NT>>>(verts, faces, out);

    // PDL: overlap finalize's launch latency with raster execution.
    cudaLaunchConfig_t cfg = {};
    cfg.gridDim  = dim3((HW + 255) / 256, 1, 1);
    cfg.blockDim = dim3(256, 1, 1);
    cfg.dynamicSmemBytes = 0;
    cfg.stream = 0;
    cudaLaunchAttribute attrs[1];
    attrs[0].id = cudaLaunchAttributeProgrammaticStreamSerialization;
    attrs[0].val.programmaticStreamSerializationAllowed = 1;
    cfg.attrs = attrs;
    cfg.numAttrs = 1;
    cudaLaunchKernelEx(&cfg, finalize_kernel, gt, out);
}